// round 8
// baseline (speedup 1.0000x reference)
#include <cuda_runtime.h>
#include <cuda_fp16.h>
#include <math.h>
#include <mma.h>

using namespace nvcuda;

#define N_NODES   100000
#define N_EDGES   1600000
#define NUM_GRAPHS 64
#define IN_CH     128
#define HID       64
#define NUM_CLASSES 10

#define SCAN_BS   256
#define SCAN_IT   4
#define SCAN_CHUNK (SCAN_BS * SCAN_IT)
#define SCAN_NBLK ((N_NODES + SCAN_CHUNK - 1) / SCAN_CHUNK)  // 98
#define LB_FLAG   (1 << 30)

// ---------------- scratch ----------------
__device__ int   g_cnt[N_NODES];            // zero-init; scatter restores to zero
__device__ float g_dinv[N_NODES];
__device__ int   g_rowptr[N_NODES + 1];
__device__ int2  g_edge[N_EDGES];
__device__ int   g_look[SCAN_NBLK];
__device__ __align__(16) __half g_W1h[IN_CH * HID];
__device__ __align__(16) __half g_W2h[HID * HID];
__device__ __align__(128) __half g_th[(size_t)N_NODES * HID];  // GEMM outputs (also t10 home)
__device__ __align__(128) __half g_hh[(size_t)N_NODES * HID];  // prop outputs
__device__ float g_pool[NUM_GRAPHS * NUM_CLASSES];  // zero-init; final restores
__device__ float g_pcnt[NUM_GRAPHS];

// ---------------- W -> half (once per call, trivial) ----------------
__global__ void wconv_kernel(const float* __restrict__ W1, const float* __restrict__ W2) {
    int i = blockIdx.x * blockDim.x + threadIdx.x;
    if (i < IN_CH * HID) g_W1h[i] = __float2half(W1[i]);
    if (i < HID * HID)   g_W2h[i] = __float2half(W2[i]);
}

// ---------------- degree count (+ clears lookback words) ----------------
__global__ void count_kernel(const int* __restrict__ ei) {
    int e = blockIdx.x * blockDim.x + threadIdx.x;
    if (e < SCAN_NBLK) g_look[e] = 0;
    if (e < N_EDGES) atomicAdd(&g_cnt[ei[N_EDGES + e]], 1);
}

// ---------------- fused dinv + exclusive scan (decoupled lookback) ----------------
__global__ void build_rowptr() {
    int b = blockIdx.x, t = threadIdx.x;
    int lane = t & 31, warp = t >> 5;
    int i0 = b * SCAN_CHUNK + t * SCAN_IT;
    int v[SCAN_IT]; int s = 0;
    #pragma unroll
    for (int i = 0; i < SCAN_IT; i++) {
        int idx = i0 + i;
        int c = 0;
        if (idx < N_NODES) {
            c = g_cnt[idx];
            g_dinv[idx] = rsqrtf((float)(c + 1));
        }
        s += c; v[i] = s;
    }
    int x = s;
    #pragma unroll
    for (int off = 1; off < 32; off <<= 1) {
        int y = __shfl_up_sync(0xffffffffu, x, off);
        if (lane >= off) x += y;
    }
    __shared__ int ws[8];
    __shared__ int s_base;
    if (lane == 31) ws[warp] = x;
    if (t == 0) s_base = 0;

    int contrib = 0;
    if (t < b) {
        volatile int* lk = (volatile int*)&g_look[t];
        int val = *lk;
        while (val < LB_FLAG) { __nanosleep(64); val = *lk; }
        contrib = val - LB_FLAG;
    }
    __syncthreads();
    if (warp == 0 && lane < 8) {
        int w = ws[lane];
        int iw = w;
        #pragma unroll
        for (int off = 1; off < 8; off <<= 1) {
            int y = __shfl_up_sync(0xffu, iw, off);
            if (lane >= off) iw += y;
        }
        ws[lane] = iw - w;
        if (lane == 7) atomicExch(&g_look[b], iw | LB_FLAG);
    }
    #pragma unroll
    for (int off = 16; off; off >>= 1) contrib += __shfl_down_sync(0xffffffffu, contrib, off);
    if (lane == 0 && contrib) atomicAdd(&s_base, contrib);
    __syncthreads();

    int excl = s_base + ws[warp] + (x - s);
    #pragma unroll
    for (int i = 0; i < SCAN_IT; i++) {
        int idx = i0 + i;
        if (idx < N_NODES) g_rowptr[idx + 1] = excl + v[i];
    }
    if (b == 0 && t == 0) g_rowptr[0] = 0;
}

// ---------------- CSR scatter ----------------
__global__ void scatter_kernel(const int* __restrict__ ei) {
    int e = blockIdx.x * blockDim.x + threadIdx.x;
    if (e < N_EDGES) {
        int s = ei[e];
        int d = ei[N_EDGES + e];
        int pos = g_rowptr[d] + atomicSub(&g_cnt[d], 1) - 1;
        g_edge[pos] = make_int2(s, __float_as_int(g_dinv[s] * g_dinv[d]));
    }
}

// ---------------- single-stage HMMA GEMM: [n x K] @ [K x 64] -> half [n x 64] ----------------
template <int K, typename TA>
__global__ void gemm64_hmma(const TA* __restrict__ A, const __half* __restrict__ Wh,
                            __half* __restrict__ C, int n) {
    constexpr int AST = K + 8;
    extern __shared__ char smraw[];
    __half (*Ash)[AST] = reinterpret_cast<__half(*)[AST]>(smraw);
    __half (*Wsh)[72]  = reinterpret_cast<__half(*)[72]>(smraw + 128 * AST * 2);
    float* Cs = reinterpret_cast<float*>(smraw);
    int tid = threadIdx.x, wid = tid >> 5, lane = tid & 31;
    int wm = wid >> 1, wn = wid & 1;
    int n0 = blockIdx.x * 128;

    #pragma unroll
    for (int i = tid; i < K * 8; i += 256) {
        uint4 q = reinterpret_cast<const uint4*>(Wh)[i];
        int k = (i * 8) >> 6, c = (i * 8) & 63;
        *reinterpret_cast<uint4*>(&Wsh[k][c]) = q;
    }

    if constexpr (sizeof(TA) == 4) {
        #pragma unroll
        for (int i = 0; i < (128 * K / 4) / 256; i++) {
            int f4 = tid + i * 256;
            int r  = f4 / (K / 4);
            int c4 = (f4 % (K / 4)) * 4;
            int gr = n0 + r;
            float4 v = (gr < n)
                ? *reinterpret_cast<const float4*>((const float*)A + (size_t)gr * K + c4)
                : make_float4(0.f, 0.f, 0.f, 0.f);
            __half2* dst = reinterpret_cast<__half2*>(&Ash[r][c4]);
            dst[0] = __floats2half2_rn(v.x, v.y);
            dst[1] = __floats2half2_rn(v.z, v.w);
        }
    } else {
        #pragma unroll
        for (int i = 0; i < (128 * K / 8) / 256; i++) {
            int u = tid + i * 256;
            int r  = u / (K / 8);
            int c8 = (u % (K / 8)) * 8;
            int gr = n0 + r;
            uint4 q = (gr < n)
                ? *reinterpret_cast<const uint4*>((const __half*)A + (size_t)gr * K + c8)
                : make_uint4(0u, 0u, 0u, 0u);
            *reinterpret_cast<uint4*>(&Ash[r][c8]) = q;
        }
    }
    __syncthreads();

    wmma::fragment<wmma::accumulator, 16, 16, 16, float> cf[2][2];
    #pragma unroll
    for (int mm = 0; mm < 2; mm++)
        #pragma unroll
        for (int nn = 0; nn < 2; nn++)
            wmma::fill_fragment(cf[mm][nn], 0.0f);

    #pragma unroll
    for (int ks = 0; ks < K / 16; ks++) {
        wmma::fragment<wmma::matrix_a, 16, 16, 16, __half, wmma::row_major> af[2];
        wmma::fragment<wmma::matrix_b, 16, 16, 16, __half, wmma::row_major> bf[2];
        #pragma unroll
        for (int mm = 0; mm < 2; mm++)
            wmma::load_matrix_sync(af[mm], &Ash[wm * 32 + mm * 16][ks * 16], AST);
        #pragma unroll
        for (int nn = 0; nn < 2; nn++)
            wmma::load_matrix_sync(bf[nn], &Wsh[ks * 16][wn * 32 + nn * 16], 72);
        #pragma unroll
        for (int mm = 0; mm < 2; mm++)
            #pragma unroll
            for (int nn = 0; nn < 2; nn++)
                wmma::mma_sync(cf[mm][nn], af[mm], bf[nn], cf[mm][nn]);
    }
    __syncthreads();

    float* Cw = Cs + wid * (32 * 36);
    #pragma unroll
    for (int mm = 0; mm < 2; mm++)
        #pragma unroll
        for (int nn = 0; nn < 2; nn++)
            wmma::store_matrix_sync(Cw + mm * 16 * 36 + nn * 16, cf[mm][nn], 36, wmma::mem_row_major);
    __syncwarp();

    int gr = n0 + wm * 32 + lane;
    if (gr < n) {
        __half2* dst = reinterpret_cast<__half2*>(C + (size_t)gr * 64 + wn * 32);
        const float* src = Cw + lane * 36;
        #pragma unroll
        for (int cc = 0; cc < 16; cc++)
            dst[cc] = __floats2half2_rn(src[cc * 2], src[cc * 2 + 1]);
    }
}

// ---------------- GEMM: half [n x 64] @ [64 x 10] -> half [n x 10] ----------------
__global__ void gemm_out10(const __half* __restrict__ A, const float* __restrict__ W,
                           __half* __restrict__ C, int n) {
    __shared__ float Ws[64][10];
    __shared__ float As[16][257];
    int tid = threadIdx.x;
    for (int i = tid; i < 640; i += 256) Ws[i / 10][i % 10] = W[i];
    int n0 = blockIdx.x * 256;
    float acc[10];
    #pragma unroll
    for (int c = 0; c < 10; c++) acc[c] = 0.f;

    for (int k0 = 0; k0 < 64; k0 += 16) {
        #pragma unroll
        for (int i = 0; i < 2; i++) {
            int u = tid + i * 256;
            int node = u >> 1;
            int c8 = (u & 1) * 8;
            int gn = n0 + node;
            uint4 q = (gn < n)
                ? *reinterpret_cast<const uint4*>(A + (size_t)gn * 64 + k0 + c8)
                : make_uint4(0u, 0u, 0u, 0u);
            float2 f0 = __half22float2(*reinterpret_cast<__half2*>(&q.x));
            float2 f1 = __half22float2(*reinterpret_cast<__half2*>(&q.y));
            float2 f2 = __half22float2(*reinterpret_cast<__half2*>(&q.z));
            float2 f3 = __half22float2(*reinterpret_cast<__half2*>(&q.w));
            As[c8 + 0][node] = f0.x; As[c8 + 1][node] = f0.y;
            As[c8 + 2][node] = f1.x; As[c8 + 3][node] = f1.y;
            As[c8 + 4][node] = f2.x; As[c8 + 5][node] = f2.y;
            As[c8 + 6][node] = f3.x; As[c8 + 7][node] = f3.y;
        }
        __syncthreads();
        #pragma unroll
        for (int kk = 0; kk < 16; kk++) {
            float a = As[kk][tid];
            #pragma unroll
            for (int c = 0; c < 10; c++) acc[c] += a * Ws[k0 + kk][c];
        }
        __syncthreads();
    }
    int gn = n0 + tid;
    if (gn < n) {
        __half2* dst = reinterpret_cast<__half2*>(C + (size_t)gn * 10);
        #pragma unroll
        for (int c = 0; c < 5; c++)
            dst[c] = __floats2half2_rn(acc[2 * c], acc[2 * c + 1]);
    }
}

// ---------------- propagation, 64 ch fp16 -> fp16: warp per node, uniform edge loads ----------------
__global__ void prop64(const __half* __restrict__ Hin, __half* __restrict__ Hout,
                       const float* __restrict__ bias, int n, int do_relu) {
    int gtid = blockIdx.x * blockDim.x + threadIdx.x;
    int v = gtid >> 5;
    int lane = threadIdx.x & 31;
    if (v >= n) return;

    const __half2* __restrict__ H2 = reinterpret_cast<const __half2*>(Hin);
    float dv = g_dinv[v];
    float selfn = dv * dv;
    float2 xv = __half22float2(H2[(size_t)v * 32 + lane]);
    float2 acc = make_float2(selfn * xv.x, selfn * xv.y);

    int e0 = g_rowptr[v];
    int m  = g_rowptr[v + 1] - e0;
    const int2* __restrict__ ep = g_edge + e0;

    int j = 0;
    for (; j + 8 <= m; j += 8) {
        #pragma unroll
        for (int q = 0; q < 8; q++) {
            int2 e = ep[j + q];
            float nm = __int_as_float(e.y);
            float2 hh = __half22float2(H2[(size_t)e.x * 32 + lane]);
            acc.x += nm * hh.x;
            acc.y += nm * hh.y;
        }
    }
    #pragma unroll 7
    for (; j < m; j++) {
        int2 e = ep[j];
        float nm = __int_as_float(e.y);
        float2 hh = __half22float2(H2[(size_t)e.x * 32 + lane]);
        acc.x += nm * hh.x;
        acc.y += nm * hh.y;
    }

    float2 b = reinterpret_cast<const float2*>(bias)[lane];
    acc.x += b.x; acc.y += b.y;
    if (do_relu) {
        acc.x = fmaxf(acc.x, 0.f);
        acc.y = fmaxf(acc.y, 0.f);
    }
    reinterpret_cast<__half2*>(Hout)[(size_t)v * 32 + lane] = __floats2half2_rn(acc.x, acc.y);
}

// ---------------- propagation 10ch (half in) + fused mean-pool, uniform edge loads ----------------
__global__ void prop10_pool(const __half* __restrict__ Hin, const float* __restrict__ bias,
                            const int* __restrict__ batch, int n) {
    int gtid = blockIdx.x * blockDim.x + threadIdx.x;
    int v = gtid >> 5;
    int lane = threadIdx.x & 31;
    if (v >= n) return;

    float dv = g_dinv[v];
    float selfn = dv * dv;
    float acc = 0.f;
    if (lane < NUM_CLASSES) acc = selfn * __half2float(Hin[(size_t)v * 10 + lane]);

    int e0 = g_rowptr[v];
    int m  = g_rowptr[v + 1] - e0;
    const int2* __restrict__ ep = g_edge + e0;

    int j = 0;
    for (; j + 8 <= m; j += 8) {
        #pragma unroll
        for (int q = 0; q < 8; q++) {
            int2 e = ep[j + q];
            float nm = __int_as_float(e.y);
            if (lane < NUM_CLASSES)
                acc += nm * __half2float(Hin[(size_t)e.x * 10 + lane]);
        }
    }
    #pragma unroll 7
    for (; j < m; j++) {
        int2 e = ep[j];
        float nm = __int_as_float(e.y);
        if (lane < NUM_CLASSES)
            acc += nm * __half2float(Hin[(size_t)e.x * 10 + lane]);
    }

    int g = batch[v];
    if (lane < NUM_CLASSES)
        atomicAdd(&g_pool[g * 10 + lane], acc + bias[lane]);
    if (lane == NUM_CLASSES)
        atomicAdd(&g_pcnt[g], 1.f);
}

// ---------------- final mean + log_softmax (self-restoring) ----------------
__global__ void final_kernel(float* __restrict__ out) {
    int g = threadIdx.x;
    if (g >= NUM_GRAPHS) return;
    float inv = 1.f / fmaxf(g_pcnt[g], 1.f);
    float v[NUM_CLASSES];
    float m = -1e30f;
    #pragma unroll
    for (int c = 0; c < NUM_CLASSES; c++) {
        v[c] = g_pool[g * 10 + c] * inv;
        m = fmaxf(m, v[c]);
    }
    float ssum = 0.f;
    #pragma unroll
    for (int c = 0; c < NUM_CLASSES; c++) ssum += expf(v[c] - m);
    float lse = m + logf(ssum);
    #pragma unroll
    for (int c = 0; c < NUM_CLASSES; c++) {
        out[g * 10 + c] = v[c] - lse;
        g_pool[g * 10 + c] = 0.f;
    }
    g_pcnt[g] = 0.f;
}

// ---------------- launch ----------------
extern "C" void kernel_launch(void* const* d_in, const int* in_sizes, int n_in,
                              void* d_out, int out_size) {
    const float* x   = (const float*)d_in[0];
    const int*   ei  = (const int*)d_in[1];
    const int*   bat = (const int*)d_in[2];
    const float* W1  = (const float*)d_in[3];
    const float* b1  = (const float*)d_in[4];
    const float* W2  = (const float*)d_in[5];
    const float* b2  = (const float*)d_in[6];
    const float* W3  = (const float*)d_in[7];
    const float* b3  = (const float*)d_in[8];
    float* out = (float*)d_out;

    __half* th = nullptr; __half* hh = nullptr;
    __half* w1h = nullptr; __half* w2h = nullptr;
    cudaGetSymbolAddress((void**)&th, g_th);
    cudaGetSymbolAddress((void**)&hh, g_hh);
    cudaGetSymbolAddress((void**)&w1h, g_W1h);
    cudaGetSymbolAddress((void**)&w2h, g_W2h);

    const size_t GSM1 = (size_t)128 * (IN_CH + 8) * 2 + (size_t)IN_CH * 72 * 2;  // 53248
    const size_t GSM2_raw = (size_t)128 * (HID + 8) * 2 + (size_t)HID * 72 * 2;  // 27648
    const size_t GSM2 = GSM2_raw > 36864 ? GSM2_raw : 36864;

    static cudaStream_t s2 = nullptr;
    static cudaEvent_t evFork = nullptr, evJoin = nullptr;
    if (s2 == nullptr) {
        cudaStreamCreateWithFlags(&s2, cudaStreamNonBlocking);
        cudaEventCreateWithFlags(&evFork, cudaEventDisableTiming);
        cudaEventCreateWithFlags(&evJoin, cudaEventDisableTiming);
        cudaFuncSetAttribute(gemm64_hmma<IN_CH, float>,
                             cudaFuncAttributeMaxDynamicSharedMemorySize, (int)GSM1);
        cudaFuncSetAttribute(gemm64_hmma<HID, __half>,
                             cudaFuncAttributeMaxDynamicSharedMemorySize, (int)GSM2);
    }

    const int TB = 256;
    int nblk  = (N_NODES + TB - 1) / TB;
    int eblk  = (N_EDGES + TB - 1) / TB;
    int wblk  = (N_NODES * 32 + TB - 1) / TB;
    int gblk  = (N_NODES + 127) / 128;

    // ---- fork: CSR preprocessing on s2, W-convert + GEMM-1 on main ----
    cudaEventRecord(evFork, 0);
    cudaStreamWaitEvent(s2, evFork, 0);

    count_kernel<<<eblk, TB, 0, s2>>>(ei);
    build_rowptr<<<SCAN_NBLK, SCAN_BS, 0, s2>>>();
    scatter_kernel<<<eblk, TB, 0, s2>>>(ei);
    cudaEventRecord(evJoin, s2);

    wconv_kernel<<<(IN_CH * HID + TB - 1) / TB, TB>>>(W1, W2);
    gemm64_hmma<IN_CH, float><<<gblk, TB, GSM1>>>(x, w1h, th, N_NODES);

    cudaStreamWaitEvent(0, evJoin, 0);

    prop64<<<wblk, TB>>>(th, hh, b1, N_NODES, 1);
    gemm64_hmma<HID, __half><<<gblk, TB, GSM2>>>(hh, w2h, th, N_NODES);
    prop64<<<wblk, TB>>>(th, hh, b2, N_NODES, 1);
    gemm_out10<<<nblk, TB>>>(hh, W3, th, N_NODES);   // t10 (half) stored in g_th
    prop10_pool<<<wblk, TB>>>(th, b3, bat, N_NODES);

    final_kernel<<<1, 64>>>(out);
}